// round 11
// baseline (speedup 1.0000x reference)
#include <cuda_runtime.h>

#define B_   256
#define T_   1000
#define H_   256
#define DIN  64
#define DOUT 64
#define NC_  10
#define R_   4
#define G_   (B_ / R_)          /* 64 CTAs */
#define NTHR 512
#define STEPS (T_ - 1)
#define LOGITS_OFF ((size_t)B_ * (size_t)T_ * (size_t)DOUT)
#define KP   128                /* k-pairs per phase (256 k / 2) */
#define GRP  8                  /* k-pairs per prefetch group */
#define NGRP (KP / 2 / GRP)     /* 8 groups per half-phase */

// ---------------------------------------------------------------------------
// Device scratch (recomputed every call).
// g_WA[k2][j] = {Af[j][1+2k2], Ag[j][1+2k2], Af[j][2+2k2], Ag[j][2+2k2]}
// g_WB[k2][n] = {Wf2[n][2k2],  Wg2[n][2k2],  Wf2[n][2k2+1], Wg2[n][2k2+1]}
// ---------------------------------------------------------------------------
__device__ float4 g_WA[KP][H_];
__device__ float4 g_WB[KP][H_];
__device__ float  g_WdT[H_][DOUT];    // Wd transposed: [k][m]
__device__ float2 g_a0 [H_];          // time-row of fused A: {Af[j][0], Ag[j][0]}
__device__ float2 g_cfg[H_];          // {Wf1@b_in+bf1, Wg1@bn+bg1}
__device__ float2 g_b2 [H_];          // {bf2, bg2}

// ---------------------------------------------------------------------------
// Packed fp32x2 helpers (PTX-only dual-rate fp32 path).
// ---------------------------------------------------------------------------
typedef unsigned long long u64;
__device__ __forceinline__ void ffma2(u64& acc, u64 a, u64 b) {
    asm("fma.rn.f32x2 %0, %1, %2, %0;" : "+l"(acc) : "l"(a), "l"(b));
}
__device__ __forceinline__ u64 fadd2(u64 a, u64 b) {
    u64 r; asm("add.rn.f32x2 %0, %1, %2;" : "=l"(r) : "l"(a), "l"(b)); return r;
}
__device__ __forceinline__ u64 pack2(float lo, float hi) {
    u64 r;
    asm("mov.b64 %0, {%1, %2};" : "=l"(r)
        : "r"(__float_as_uint(lo)), "r"(__float_as_uint(hi)));
    return r;
}
__device__ __forceinline__ float lo2(u64 v) {
    return __uint_as_float((unsigned)(v & 0xffffffffull));
}
__device__ __forceinline__ float hi2(u64 v) {
    return __uint_as_float((unsigned)(v >> 32));
}
__device__ __forceinline__ u64 dup_lo(u64 v) { float f = lo2(v); return pack2(f, f); }
__device__ __forceinline__ u64 dup_hi(u64 v) { float f = hi2(v); return pack2(f, f); }
__device__ __forceinline__ float lipswish(float x) {
    return 0.909f * x / (1.0f + expf(-x));
}

// ---------------------------------------------------------------------------
// Prep 1: fuse the linear pairs; emit k-pair layout.
// ---------------------------------------------------------------------------
__global__ __launch_bounds__(256) void sde_prep_fuse(
    const float* __restrict__ W_in, const float* __restrict__ b_in,
    const float* __restrict__ Wf1,  const float* __restrict__ bf1,
    const float* __restrict__ Wn,   const float* __restrict__ bn,
    const float* __restrict__ Wg1,  const float* __restrict__ bg1)
{
    __shared__ float cin[H_], cn[H_];
    const int j = threadIdx.x;
    const int k = blockIdx.x;                 // 0..257
    if (k < H_ + 1) { cin[j] = W_in[j * (H_ + 1) + k]; cn[j] = Wn[j * (H_ + 1) + k]; }
    else            { cin[j] = b_in[j];                cn[j]  = bn[j]; }
    __syncthreads();
    const float* wf1r = Wf1 + (size_t)j * H_;
    const float* wg1r = Wg1 + (size_t)j * H_;
    float af = 0.f, ag = 0.f;
#pragma unroll 8
    for (int m = 0; m < H_; m++) {
        af = fmaf(wf1r[m], cin[m], af);
        ag = fmaf(wg1r[m], cn[m],  ag);
    }
    if (k == 0) {
        g_a0[j] = make_float2(af, ag);
    } else if (k <= H_) {
        const int k2 = (k - 1) >> 1, pos = (k - 1) & 1;
        float* p = reinterpret_cast<float*>(&g_WA[k2][j]);
        p[2 * pos] = af; p[2 * pos + 1] = ag;
    } else {
        g_cfg[j] = make_float2(af + bf1[j], ag + bg1[j]);
    }
}

// ---------------------------------------------------------------------------
// Prep 2: transpose second-layer weights into k-pair layout; transpose Wd.
// ---------------------------------------------------------------------------
__global__ __launch_bounds__(256) void sde_prep_w2(
    const float* __restrict__ Wf2, const float* __restrict__ bf2,
    const float* __restrict__ Wg2, const float* __restrict__ bg2,
    const float* __restrict__ Wd)
{
    const int n = threadIdx.x;
    const int k = blockIdx.x;                 // 0..255
    const int k2 = k >> 1, pos = k & 1;
    float* p = reinterpret_cast<float*>(&g_WB[k2][n]);
    p[2 * pos]     = Wf2[(size_t)n * H_ + k];
    p[2 * pos + 1] = Wg2[(size_t)n * H_ + k];
    if (k == 0) g_b2[n] = make_float2(bf2[n], bg2[n]);
    if (n < DOUT) g_WdT[k][n] = Wd[(size_t)n * H_ + k];
}

// ---------------------------------------------------------------------------
// Main persistent kernel: 64 CTAs x 512 threads; two k-halves (half = tid>>8),
// j = tid & 255; each CTA owns 4 batch rows for all 999 steps.
// ---------------------------------------------------------------------------
__global__ __launch_bounds__(NTHR, 1) void sde_main(
    const float* __restrict__ coeffs, const float* __restrict__ times,
    const int*   __restrict__ mask,   const float* __restrict__ noise,
    const float* __restrict__ W0,     const float* __restrict__ b0,
    const float* __restrict__ bd,
    const float* __restrict__ Wc,     const float* __restrict__ bc,
    float* __restrict__ out)
{
    __shared__ float2 s_y01[H_];        // {y_row0, y_row1}[k]
    __shared__ float2 s_y23[H_];
    __shared__ float2 s_hfg[R_][H_];    // {hf_r, hg_r}[k]
    __shared__ ulonglong2 s_redA[H_];   // cross-half partials (conflict-free)
    __shared__ ulonglong2 s_redB[H_];
    __shared__ float4 s_part[8][DOUT];  // pred partials per 32-k chunk
    __shared__ float  s_zf[R_][H_];
    __shared__ float  s_tm[T_];
    __shared__ float  s_x0[R_][DIN];
    __shared__ int    s_len[R_];

    const int tid  = threadIdx.x;
    const int row0 = blockIdx.x * R_;
    const int j    = tid & 255;
    const int half = tid >> 8;
    const int kb2  = half * (KP / 2);       // this half's first k-pair

    // ---- init ----
    if (tid < R_) s_len[tid] = 0;
    for (int t = tid; t < T_; t += NTHR) s_tm[t] = times[t];
    if (tid < DIN) {
#pragma unroll
        for (int r = 0; r < R_; r++)
            s_x0[r][tid] = coeffs[(size_t)(row0 + r) * (size_t)(T_ - 1) * (4 * DIN) + tid];
    }
    __syncthreads();
    {
        int acc[R_] = {0, 0, 0, 0};
        for (int t = tid; t < T_; t += NTHR) {
#pragma unroll
            for (int r = 0; r < R_; r++) acc[r] += mask[(size_t)(row0 + r) * T_ + t];
        }
#pragma unroll
        for (int r = 0; r < R_; r++) atomicAdd(&s_len[r], acc[r]);
    }
    __syncthreads();
    int lastidx[R_];
#pragma unroll
    for (int r = 0; r < R_; r++) lastidx[r] = s_len[r] - 1;

    // ---- per-thread constants ----
    const float2 a0  = g_a0[j];
    const u64 p_af0 = pack2(a0.x, a0.x);
    const u64 p_ag0 = pack2(a0.y, a0.y);
    const float2 ccf = g_cfg[j];
    const float2 cb2 = g_b2[j];
    const int pm = tid & 63;
    const int pq = tid >> 6;                // 0..7
    const float bdv = bd[pm];

    // ---- y0 = x0 @ W0^T + b0 (half 0 owns the state) ----
    float y[R_] = {0.f, 0.f, 0.f, 0.f};
    float zfin[R_] = {0.f, 0.f, 0.f, 0.f};
    if (half == 0) {
        const float* w0r = W0 + (size_t)j * DIN;
        const float  bb  = b0[j];
#pragma unroll
        for (int r = 0; r < R_; r++) {
            float a = bb;
#pragma unroll 16
            for (int d = 0; d < DIN; d++) a = fmaf(s_x0[r][d], w0r[d], a);
            y[r] = a;
            zfin[r] = a;                    // covers lastidx == 0
        }
        s_y01[j] = make_float2(y[0], y[1]);
        s_y23[j] = make_float2(y[2], y[3]);
    }
    float t_cur = s_tm[0];
    __syncthreads();

    // ---- pred accumulate: s_part <- y @ Wd^T partials (all 512 threads) ----
    auto pred_acc = [&]() {
        u64 a01 = 0ull, a23 = 0ull;
        const int kbase = pq * 32;
        const float* wcol = &g_WdT[kbase][pm];
#pragma unroll
        for (int g = 0; g < 16; g++) {
            const float w0f = __ldg(wcol + (2 * g)     * DOUT);
            const float w1f = __ldg(wcol + (2 * g + 1) * DOUT);
            const ulonglong2 v01 = *reinterpret_cast<const ulonglong2*>(&s_y01[kbase + 2 * g]);
            const ulonglong2 v23 = *reinterpret_cast<const ulonglong2*>(&s_y23[kbase + 2 * g]);
            const u64 w0 = pack2(w0f, w0f);
            const u64 w1 = pack2(w1f, w1f);
            ffma2(a01, v01.x, w0); ffma2(a01, v01.y, w1);
            ffma2(a23, v23.x, w0); ffma2(a23, v23.y, w1);
        }
        s_part[pq][pm] = make_float4(lo2(a01), hi2(a01), lo2(a23), hi2(a23));
    };
    // ---- pred gather + store (executed by half-1's 256 threads) ----
    auto pred_gather = [&](int idx) {
        const int t  = tid - 256;
        const int r2 = t >> 6;
        float v = bdv;
#pragma unroll
        for (int qq = 0; qq < 8; qq++)
            v += reinterpret_cast<const float*>(&s_part[qq][pm])[r2];
        out[(size_t)(row0 + r2) * T_ * DOUT + (size_t)idx * DOUT + pm] = v;
    };

    // ======================= main scan: 999 steps =======================
    for (int i = 0; i < STEPS; i++) {
        // prefetch noise early (half 0)
        float eps[R_];
        if (half == 0) {
            const float* np = noise + ((size_t)i * B_ + row0) * H_ + j;
#pragma unroll
            for (int r = 0; r < R_; r++) eps[r] = __ldg(np + (size_t)r * H_);
        }

        // pred partials for index i (overlaps with phase A weight streaming)
        pred_acc();

        // ---------- phase A: pre-act = A @ [t; y] ----------
        u64 af01, ag01, af23, ag23;
        if (half == 0) {
            const u64 tt = pack2(t_cur, t_cur);
            af01 = 0ull; ffma2(af01, tt, p_af0);
            ag01 = 0ull; ffma2(ag01, tt, p_ag0);
            af23 = af01; ag23 = ag01;
        } else { af01 = ag01 = af23 = ag23 = 0ull; }
        {
            const ulonglong2* wa =
                reinterpret_cast<const ulonglong2*>(&g_WA[kb2][0]) + j;
            ulonglong2 wbuf[GRP];
#pragma unroll
            for (int p = 0; p < GRP; p++) wbuf[p] = wa[(size_t)p * H_];
#pragma unroll 1
            for (int blk = 0; blk < NGRP; blk++) {
                ulonglong2 wn[GRP];
                if (blk < NGRP - 1) {
#pragma unroll
                    for (int p = 0; p < GRP; p++)
                        wn[p] = wa[(size_t)((blk + 1) * GRP + p) * H_];
                }
#pragma unroll
                for (int p = 0; p < GRP; p++) {
                    const int k2 = kb2 + blk * GRP + p;
                    const ulonglong2 v01 =
                        *reinterpret_cast<const ulonglong2*>(&s_y01[2 * k2]);
                    const ulonglong2 v23 =
                        *reinterpret_cast<const ulonglong2*>(&s_y23[2 * k2]);
                    const u64 df0 = dup_lo(wbuf[p].x), dg0 = dup_hi(wbuf[p].x);
                    const u64 df1 = dup_lo(wbuf[p].y), dg1 = dup_hi(wbuf[p].y);
                    ffma2(af01, v01.x, df0); ffma2(ag01, v01.x, dg0);
                    ffma2(af23, v23.x, df0); ffma2(ag23, v23.x, dg0);
                    ffma2(af01, v01.y, df1); ffma2(ag01, v01.y, dg1);
                    ffma2(af23, v23.y, df1); ffma2(ag23, v23.y, dg1);
                }
#pragma unroll
                for (int p = 0; p < GRP; p++) wbuf[p] = wn[p];
            }
        }
        if (half == 1) {
            s_redA[j] = make_ulonglong2(af01, ag01);
            s_redB[j] = make_ulonglong2(af23, ag23);
        }
        __syncthreads();                                   // (1)
        if (half == 0) {
            const ulonglong2 q0 = s_redA[j], q1 = s_redB[j];
            af01 = fadd2(af01, q0.x); ag01 = fadd2(ag01, q0.y);
            af23 = fadd2(af23, q1.x); ag23 = fadd2(ag23, q1.y);
            s_hfg[0][j] = make_float2(lipswish(lo2(af01) + ccf.x),
                                      lipswish(lo2(ag01) + ccf.y));
            s_hfg[1][j] = make_float2(lipswish(hi2(af01) + ccf.x),
                                      lipswish(hi2(ag01) + ccf.y));
            s_hfg[2][j] = make_float2(lipswish(lo2(af23) + ccf.x),
                                      lipswish(lo2(ag23) + ccf.y));
            s_hfg[3][j] = make_float2(lipswish(hi2(af23) + ccf.x),
                                      lipswish(hi2(ag23) + ccf.y));
        } else {
            pred_gather(i);                                // hidden in A-reduce shadow
        }
        __syncthreads();                                   // (2)

        // ---------- phase B: {f,g} = h @ W2 ----------
        u64 b0a = 0ull, b1a = 0ull, b2a = 0ull, b3a = 0ull;
        {
            const ulonglong2* wb =
                reinterpret_cast<const ulonglong2*>(&g_WB[kb2][0]) + j;
            ulonglong2 wbuf[GRP];
#pragma unroll
            for (int p = 0; p < GRP; p++) wbuf[p] = wb[(size_t)p * H_];
#pragma unroll 1
            for (int blk = 0; blk < NGRP; blk++) {
                ulonglong2 wn[GRP];
                if (blk < NGRP - 1) {
#pragma unroll
                    for (int p = 0; p < GRP; p++)
                        wn[p] = wb[(size_t)((blk + 1) * GRP + p) * H_];
                }
#pragma unroll
                for (int p = 0; p < GRP; p++) {
                    const int k2 = kb2 + blk * GRP + p;
                    const ulonglong2 h0 =
                        *reinterpret_cast<const ulonglong2*>(&s_hfg[0][2 * k2]);
                    const ulonglong2 h1 =
                        *reinterpret_cast<const ulonglong2*>(&s_hfg[1][2 * k2]);
                    const ulonglong2 h2 =
                        *reinterpret_cast<const ulonglong2*>(&s_hfg[2][2 * k2]);
                    const ulonglong2 h3 =
                        *reinterpret_cast<const ulonglong2*>(&s_hfg[3][2 * k2]);
                    ffma2(b0a, h0.x, wbuf[p].x); ffma2(b0a, h0.y, wbuf[p].y);
                    ffma2(b1a, h1.x, wbuf[p].x); ffma2(b1a, h1.y, wbuf[p].y);
                    ffma2(b2a, h2.x, wbuf[p].x); ffma2(b2a, h2.y, wbuf[p].y);
                    ffma2(b3a, h3.x, wbuf[p].x); ffma2(b3a, h3.y, wbuf[p].y);
                }
#pragma unroll
                for (int p = 0; p < GRP; p++) wbuf[p] = wn[p];
            }
        }
        if (half == 1) {
            s_redA[j] = make_ulonglong2(b0a, b1a);
            s_redB[j] = make_ulonglong2(b2a, b3a);
        }
        __syncthreads();                                   // (3)
        if (half == 0) {
            const ulonglong2 q0 = s_redA[j], q1 = s_redB[j];
            b0a = fadd2(b0a, q0.x); b1a = fadd2(b1a, q0.y);
            b2a = fadd2(b2a, q1.x); b3a = fadd2(b3a, q1.y);
            const float t_next = s_tm[i + 1];
            const float dt = t_next - t_cur;
            const float sd = sqrtf(dt);
            u64 fg[R_] = {b0a, b1a, b2a, b3a};
#pragma unroll
            for (int r = 0; r < R_; r++) {
                const float f = lo2(fg[r]) + cb2.x;
                const float g = hi2(fg[r]) + cb2.y;
                y[r] = fmaf(f, dt, fmaf(g, sd * eps[r], y[r]));
                if (i + 1 == lastidx[r]) zfin[r] = y[r];
            }
            s_y01[j] = make_float2(y[0], y[1]);
            s_y23[j] = make_float2(y[2], y[3]);
        }
        t_cur = s_tm[i + 1];
        __syncthreads();                                   // (4)
    }

    // ---- final pred (index = STEPS) ----
    pred_acc();
    if (half == 0) {
#pragma unroll
        for (int r = 0; r < R_; r++) s_zf[r][j] = zfin[r];
    }
    __syncthreads();
    if (half == 1) pred_gather(STEPS);

    // ---- logits = z_final @ Wc^T + bc ----
    if (tid < R_ * NC_) {
        const int r = tid / NC_;
        const int c = tid % NC_;
        const float* wcr = Wc + (size_t)c * H_;
        float a = bc[c];
#pragma unroll 8
        for (int k = 0; k < H_; k++) a = fmaf(s_zf[r][k], wcr[k], a);
        out[LOGITS_OFF + (size_t)(row0 + r) * NC_ + c] = a;
    }
}

// ---------------------------------------------------------------------------
// Launch: prep (fused weights) then the persistent scan. Stream-0 only,
// allocation-free, graph-capturable.
// ---------------------------------------------------------------------------
extern "C" void kernel_launch(void* const* d_in, const int* in_sizes, int n_in,
                              void* d_out, int out_size) {
    const float* coeffs = (const float*)d_in[0];
    const float* times  = (const float*)d_in[1];
    const int*   mask   = (const int*)  d_in[2];
    const float* noise  = (const float*)d_in[3];
    const float* W_in   = (const float*)d_in[4];
    const float* b_in   = (const float*)d_in[5];
    const float* Wf1    = (const float*)d_in[6];
    const float* bf1    = (const float*)d_in[7];
    const float* Wf2    = (const float*)d_in[8];
    const float* bf2    = (const float*)d_in[9];
    const float* Wn     = (const float*)d_in[10];
    const float* bn     = (const float*)d_in[11];
    const float* Wg1    = (const float*)d_in[12];
    const float* bg1    = (const float*)d_in[13];
    const float* Wg2    = (const float*)d_in[14];
    const float* bg2    = (const float*)d_in[15];
    const float* W0     = (const float*)d_in[16];
    const float* b0     = (const float*)d_in[17];
    const float* Wd     = (const float*)d_in[18];
    const float* bd     = (const float*)d_in[19];
    const float* Wc     = (const float*)d_in[20];
    const float* bc     = (const float*)d_in[21];
    float* out = (float*)d_out;

    sde_prep_fuse<<<H_ + 2, 256>>>(W_in, b_in, Wf1, bf1, Wn, bn, Wg1, bg1);
    sde_prep_w2  <<<H_,     256>>>(Wf2, bf2, Wg2, bg2, Wd);
    sde_main     <<<G_, NTHR>>>(coeffs, times, mask, noise,
                                W0, b0, bd, Wc, bc, out);
}

// round 12
// speedup vs baseline: 1.0836x; 1.0836x over previous
#include <cuda_runtime.h>

#define B_   256
#define T_   1000
#define H_   256
#define DIN  64
#define DOUT 64
#define NC_  10
#define R_   4
#define G_   (B_ / R_)          /* 64 CTAs */
#define NTHR 512
#define STEPS (T_ - 1)
#define LOGITS_OFF ((size_t)B_ * (size_t)T_ * (size_t)DOUT)
#define KP   128                /* k-pairs per phase (256 k / 2) */
#define GRP  4                  /* k-pairs per prefetch group (L1TEX-queue safe) */
#define NGRP (KP / 2 / GRP)     /* 16 groups per half-phase */

// ---------------------------------------------------------------------------
// Device scratch (recomputed every call).
// g_WA[k2][j] = {Af[j][1+2k2], Ag[j][1+2k2], Af[j][2+2k2], Ag[j][2+2k2]}
// g_WB[k2][n] = {Wf2[n][2k2],  Wg2[n][2k2],  Wf2[n][2k2+1], Wg2[n][2k2+1]}
// ---------------------------------------------------------------------------
__device__ float4 g_WA[KP][H_];
__device__ float4 g_WB[KP][H_];
__device__ float2 g_a0 [H_];          // time-row of fused A: {Af[j][0], Ag[j][0]}
__device__ float2 g_cfg[H_];          // {Wf1@b_in+bf1, Wg1@bn+bg1}
__device__ float2 g_b2 [H_];          // {bf2, bg2}

// ---------------------------------------------------------------------------
// Packed fp32x2 helpers (PTX-only dual-rate fp32 path).
// ---------------------------------------------------------------------------
typedef unsigned long long u64;
__device__ __forceinline__ void ffma2(u64& acc, u64 a, u64 b) {
    asm("fma.rn.f32x2 %0, %1, %2, %0;" : "+l"(acc) : "l"(a), "l"(b));
}
__device__ __forceinline__ u64 fadd2(u64 a, u64 b) {
    u64 r; asm("add.rn.f32x2 %0, %1, %2;" : "=l"(r) : "l"(a), "l"(b)); return r;
}
__device__ __forceinline__ u64 pack2(float lo, float hi) {
    u64 r;
    asm("mov.b64 %0, {%1, %2};" : "=l"(r)
        : "r"(__float_as_uint(lo)), "r"(__float_as_uint(hi)));
    return r;
}
__device__ __forceinline__ float lo2(u64 v) {
    return __uint_as_float((unsigned)(v & 0xffffffffull));
}
__device__ __forceinline__ float hi2(u64 v) {
    return __uint_as_float((unsigned)(v >> 32));
}
__device__ __forceinline__ u64 dup_lo(u64 v) { float f = lo2(v); return pack2(f, f); }
__device__ __forceinline__ u64 dup_hi(u64 v) { float f = hi2(v); return pack2(f, f); }
__device__ __forceinline__ float lipswish(float x) {
    return 0.909f * x / (1.0f + __expf(-x));
}

// ---------------------------------------------------------------------------
// Prep 1: fuse the linear pairs; emit k-pair layout.
// ---------------------------------------------------------------------------
__global__ __launch_bounds__(256) void sde_prep_fuse(
    const float* __restrict__ W_in, const float* __restrict__ b_in,
    const float* __restrict__ Wf1,  const float* __restrict__ bf1,
    const float* __restrict__ Wn,   const float* __restrict__ bn,
    const float* __restrict__ Wg1,  const float* __restrict__ bg1)
{
    __shared__ float cin[H_], cn[H_];
    const int j = threadIdx.x;
    const int k = blockIdx.x;                 // 0..257
    if (k < H_ + 1) { cin[j] = W_in[j * (H_ + 1) + k]; cn[j] = Wn[j * (H_ + 1) + k]; }
    else            { cin[j] = b_in[j];                cn[j]  = bn[j]; }
    __syncthreads();
    const float* wf1r = Wf1 + (size_t)j * H_;
    const float* wg1r = Wg1 + (size_t)j * H_;
    float af = 0.f, ag = 0.f;
#pragma unroll 8
    for (int m = 0; m < H_; m++) {
        af = fmaf(wf1r[m], cin[m], af);
        ag = fmaf(wg1r[m], cn[m],  ag);
    }
    if (k == 0) {
        g_a0[j] = make_float2(af, ag);
    } else if (k <= H_) {
        const int k2 = (k - 1) >> 1, pos = (k - 1) & 1;
        float* p = reinterpret_cast<float*>(&g_WA[k2][j]);
        p[2 * pos] = af; p[2 * pos + 1] = ag;
    } else {
        g_cfg[j] = make_float2(af + bf1[j], ag + bg1[j]);
    }
}

// ---------------------------------------------------------------------------
// Prep 2: transpose second-layer weights into k-pair layout.
// ---------------------------------------------------------------------------
__global__ __launch_bounds__(256) void sde_prep_w2(
    const float* __restrict__ Wf2, const float* __restrict__ bf2,
    const float* __restrict__ Wg2, const float* __restrict__ bg2)
{
    const int n = threadIdx.x;
    const int k = blockIdx.x;                 // 0..255
    const int k2 = k >> 1, pos = k & 1;
    float* p = reinterpret_cast<float*>(&g_WB[k2][n]);
    p[2 * pos]     = Wf2[(size_t)n * H_ + k];
    p[2 * pos + 1] = Wg2[(size_t)n * H_ + k];
    if (k == 0) g_b2[n] = make_float2(bf2[n], bg2[n]);
}

// ---------------------------------------------------------------------------
// Main persistent kernel: 64 CTAs x 512 threads; two k-halves (half = tid>>8),
// j = tid & 255; each CTA owns 4 batch rows for all 999 steps.
// ---------------------------------------------------------------------------
__global__ __launch_bounds__(NTHR, 1) void sde_main(
    const float* __restrict__ coeffs, const float* __restrict__ times,
    const int*   __restrict__ mask,   const float* __restrict__ noise,
    const float* __restrict__ W0,     const float* __restrict__ b0,
    const float* __restrict__ Wd,     const float* __restrict__ bd,
    const float* __restrict__ Wc,     const float* __restrict__ bc,
    float* __restrict__ out)
{
    __shared__ float2 s_y01[H_];        // {y_row0, y_row1}[k]
    __shared__ float2 s_y23[H_];
    __shared__ float2 s_hfg[R_][H_];    // {hf_r, hg_r}[k]
    __shared__ u64    s_redA[2][H_];    // cross-half partials, 16B-stride arrays
    __shared__ u64    s_redB[2][H_];
    __shared__ float4 s_part[8][DOUT];  // pred partials per 32-k chunk
    __shared__ float  s_zf[R_][H_];
    __shared__ float  s_tm[T_];
    __shared__ float  s_x0[R_][DIN];
    __shared__ int    s_len[R_];

    const int tid  = threadIdx.x;
    const int row0 = blockIdx.x * R_;
    const int j    = tid & 255;
    const int half = tid >> 8;
    const int kb2  = half * (KP / 2);       // this half's first k-pair

    // ---- init ----
    if (tid < R_) s_len[tid] = 0;
    for (int t = tid; t < T_; t += NTHR) s_tm[t] = times[t];
    if (tid < DIN) {
#pragma unroll
        for (int r = 0; r < R_; r++)
            s_x0[r][tid] = coeffs[(size_t)(row0 + r) * (size_t)(T_ - 1) * (4 * DIN) + tid];
    }
    __syncthreads();
    {
        int acc[R_] = {0, 0, 0, 0};
        for (int t = tid; t < T_; t += NTHR) {
#pragma unroll
            for (int r = 0; r < R_; r++) acc[r] += mask[(size_t)(row0 + r) * T_ + t];
        }
#pragma unroll
        for (int r = 0; r < R_; r++) atomicAdd(&s_len[r], acc[r]);
    }
    __syncthreads();
    int lastidx[R_];
#pragma unroll
    for (int r = 0; r < R_; r++) lastidx[r] = s_len[r] - 1;

    // ---- per-thread constants ----
    const float2 a0  = g_a0[j];
    const u64 p_af0 = pack2(a0.x, a0.x);
    const u64 p_ag0 = pack2(a0.y, a0.y);
    const float2 ccf = g_cfg[j];
    const float2 cb2 = g_b2[j];
    const int pm = tid & 63;
    const int pq = tid >> 6;                // 0..7
    const float bdv = bd[pm];

    // Wd slice in registers: thread (pm, pq) owns 32 consecutive k.
    float wdr[32];
    {
        const float* p = Wd + (size_t)pm * H_ + pq * 32;
#pragma unroll
        for (int kk = 0; kk < 32; kk++) wdr[kk] = p[kk];
    }

    // ---- y0 = x0 @ W0^T + b0 (half 0 owns the state) ----
    float y[R_] = {0.f, 0.f, 0.f, 0.f};
    float zfin[R_] = {0.f, 0.f, 0.f, 0.f};
    if (half == 0) {
        const float* w0r = W0 + (size_t)j * DIN;
        const float  bb  = b0[j];
#pragma unroll
        for (int r = 0; r < R_; r++) {
            float a = bb;
#pragma unroll 16
            for (int d = 0; d < DIN; d++) a = fmaf(s_x0[r][d], w0r[d], a);
            y[r] = a;
            zfin[r] = a;                    // covers lastidx == 0
        }
        s_y01[j] = make_float2(y[0], y[1]);
        s_y23[j] = make_float2(y[2], y[3]);
    }
    float t_cur = s_tm[0];
    __syncthreads();

    // ---- pred accumulate: s_part <- y @ Wd^T partials (all 512 threads) ----
    auto pred_acc = [&]() {
        u64 a01 = 0ull, a23 = 0ull;
        const int kbase = pq * 32;
#pragma unroll
        for (int g = 0; g < 16; g++) {
            const ulonglong2 v01 = *reinterpret_cast<const ulonglong2*>(&s_y01[kbase + 2 * g]);
            const ulonglong2 v23 = *reinterpret_cast<const ulonglong2*>(&s_y23[kbase + 2 * g]);
            const u64 w0 = pack2(wdr[2 * g],     wdr[2 * g]);
            const u64 w1 = pack2(wdr[2 * g + 1], wdr[2 * g + 1]);
            ffma2(a01, v01.x, w0); ffma2(a01, v01.y, w1);
            ffma2(a23, v23.x, w0); ffma2(a23, v23.y, w1);
        }
        s_part[pq][pm] = make_float4(lo2(a01), hi2(a01), lo2(a23), hi2(a23));
    };
    // ---- pred gather + store (executed by half-1's 256 threads) ----
    auto pred_gather = [&](int idx) {
        const int t  = tid - 256;
        const int r2 = t >> 6;
        float v = bdv;
#pragma unroll
        for (int qq = 0; qq < 8; qq++)
            v += reinterpret_cast<const float*>(&s_part[qq][pm])[r2];
        out[(size_t)(row0 + r2) * T_ * DOUT + (size_t)idx * DOUT + pm] = v;
    };

    // ======================= main scan: 999 steps =======================
    for (int i = 0; i < STEPS; i++) {
        // prefetch noise early (half 0)
        float eps[R_];
        if (half == 0) {
            const float* np = noise + ((size_t)i * B_ + row0) * H_ + j;
#pragma unroll
            for (int r = 0; r < R_; r++) eps[r] = __ldg(np + (size_t)r * H_);
        }

        // pred partials for index i (overlaps phase-A weight streaming)
        pred_acc();

        // ---------- phase A: pre-act = A @ [t; y] ----------
        u64 af01, ag01, af23, ag23;
        if (half == 0) {
            const u64 tt = pack2(t_cur, t_cur);
            af01 = 0ull; ffma2(af01, tt, p_af0);
            ag01 = 0ull; ffma2(ag01, tt, p_ag0);
            af23 = af01; ag23 = ag01;
        } else { af01 = ag01 = af23 = ag23 = 0ull; }
        {
            const ulonglong2* wa =
                reinterpret_cast<const ulonglong2*>(&g_WA[kb2][0]) + j;
            ulonglong2 wbuf[GRP];
#pragma unroll
            for (int p = 0; p < GRP; p++) wbuf[p] = wa[(size_t)p * H_];
#pragma unroll 1
            for (int blk = 0; blk < NGRP; blk++) {
                ulonglong2 wn[GRP];
                if (blk < NGRP - 1) {
#pragma unroll
                    for (int p = 0; p < GRP; p++)
                        wn[p] = wa[(size_t)((blk + 1) * GRP + p) * H_];
                }
#pragma unroll
                for (int p = 0; p < GRP; p++) {
                    const int k2 = kb2 + blk * GRP + p;
                    const ulonglong2 v01 =
                        *reinterpret_cast<const ulonglong2*>(&s_y01[2 * k2]);
                    const ulonglong2 v23 =
                        *reinterpret_cast<const ulonglong2*>(&s_y23[2 * k2]);
                    const u64 df0 = dup_lo(wbuf[p].x), dg0 = dup_hi(wbuf[p].x);
                    const u64 df1 = dup_lo(wbuf[p].y), dg1 = dup_hi(wbuf[p].y);
                    ffma2(af01, v01.x, df0); ffma2(ag01, v01.x, dg0);
                    ffma2(af23, v23.x, df0); ffma2(ag23, v23.x, dg0);
                    ffma2(af01, v01.y, df1); ffma2(ag01, v01.y, dg1);
                    ffma2(af23, v23.y, df1); ffma2(ag23, v23.y, dg1);
                }
#pragma unroll
                for (int p = 0; p < GRP; p++) wbuf[p] = wn[p];
            }
        }
        if (half == 1) {
            s_redA[0][j] = af01; s_redA[1][j] = ag01;
            s_redB[0][j] = af23; s_redB[1][j] = ag23;
        }
        __syncthreads();                                   // (1)
        if (half == 0) {
            af01 = fadd2(af01, s_redA[0][j]); ag01 = fadd2(ag01, s_redA[1][j]);
            af23 = fadd2(af23, s_redB[0][j]); ag23 = fadd2(ag23, s_redB[1][j]);
            s_hfg[0][j] = make_float2(lipswish(lo2(af01) + ccf.x),
                                      lipswish(lo2(ag01) + ccf.y));
            s_hfg[1][j] = make_float2(lipswish(hi2(af01) + ccf.x),
                                      lipswish(hi2(ag01) + ccf.y));
            s_hfg[2][j] = make_float2(lipswish(lo2(af23) + ccf.x),
                                      lipswish(lo2(ag23) + ccf.y));
            s_hfg[3][j] = make_float2(lipswish(hi2(af23) + ccf.x),
                                      lipswish(hi2(ag23) + ccf.y));
        } else {
            pred_gather(i);                 // hidden in half-0's reduce shadow
        }
        __syncthreads();                                   // (2)

        // ---------- phase B: {f,g} = h @ W2 ----------
        u64 b0a = 0ull, b1a = 0ull, b2a = 0ull, b3a = 0ull;
        {
            const ulonglong2* wb =
                reinterpret_cast<const ulonglong2*>(&g_WB[kb2][0]) + j;
            ulonglong2 wbuf[GRP];
#pragma unroll
            for (int p = 0; p < GRP; p++) wbuf[p] = wb[(size_t)p * H_];
#pragma unroll 1
            for (int blk = 0; blk < NGRP; blk++) {
                ulonglong2 wn[GRP];
                if (blk < NGRP - 1) {
#pragma unroll
                    for (int p = 0; p < GRP; p++)
                        wn[p] = wb[(size_t)((blk + 1) * GRP + p) * H_];
                }
#pragma unroll
                for (int p = 0; p < GRP; p++) {
                    const int k2 = kb2 + blk * GRP + p;
                    const ulonglong2 h0 =
                        *reinterpret_cast<const ulonglong2*>(&s_hfg[0][2 * k2]);
                    const ulonglong2 h1 =
                        *reinterpret_cast<const ulonglong2*>(&s_hfg[1][2 * k2]);
                    const ulonglong2 h2 =
                        *reinterpret_cast<const ulonglong2*>(&s_hfg[2][2 * k2]);
                    const ulonglong2 h3 =
                        *reinterpret_cast<const ulonglong2*>(&s_hfg[3][2 * k2]);
                    ffma2(b0a, h0.x, wbuf[p].x); ffma2(b0a, h0.y, wbuf[p].y);
                    ffma2(b1a, h1.x, wbuf[p].x); ffma2(b1a, h1.y, wbuf[p].y);
                    ffma2(b2a, h2.x, wbuf[p].x); ffma2(b2a, h2.y, wbuf[p].y);
                    ffma2(b3a, h3.x, wbuf[p].x); ffma2(b3a, h3.y, wbuf[p].y);
                }
#pragma unroll
                for (int p = 0; p < GRP; p++) wbuf[p] = wn[p];
            }
        }
        if (half == 1) {
            s_redA[0][j] = b0a; s_redA[1][j] = b1a;
            s_redB[0][j] = b2a; s_redB[1][j] = b3a;
        }
        __syncthreads();                                   // (3)
        if (half == 0) {
            b0a = fadd2(b0a, s_redA[0][j]); b1a = fadd2(b1a, s_redA[1][j]);
            b2a = fadd2(b2a, s_redB[0][j]); b3a = fadd2(b3a, s_redB[1][j]);
            const float t_next = s_tm[i + 1];
            const float dt = t_next - t_cur;
            const float sd = sqrtf(dt);
            u64 fg[R_] = {b0a, b1a, b2a, b3a};
#pragma unroll
            for (int r = 0; r < R_; r++) {
                const float f = lo2(fg[r]) + cb2.x;
                const float g = hi2(fg[r]) + cb2.y;
                y[r] = fmaf(f, dt, fmaf(g, sd * eps[r], y[r]));
                if (i + 1 == lastidx[r]) zfin[r] = y[r];
            }
            s_y01[j] = make_float2(y[0], y[1]);
            s_y23[j] = make_float2(y[2], y[3]);
        }
        t_cur = s_tm[i + 1];
        __syncthreads();                                   // (4)
    }

    // ---- final pred (index = STEPS) ----
    pred_acc();
    if (half == 0) {
#pragma unroll
        for (int r = 0; r < R_; r++) s_zf[r][j] = zfin[r];
    }
    __syncthreads();
    if (half == 1) pred_gather(STEPS);

    // ---- logits = z_final @ Wc^T + bc ----
    if (tid < R_ * NC_) {
        const int r = tid / NC_;
        const int c = tid % NC_;
        const float* wcr = Wc + (size_t)c * H_;
        float a = bc[c];
#pragma unroll 8
        for (int k = 0; k < H_; k++) a = fmaf(s_zf[r][k], wcr[k], a);
        out[LOGITS_OFF + (size_t)(row0 + r) * NC_ + c] = a;
    }
}

// ---------------------------------------------------------------------------
// Launch: prep (fused weights) then the persistent scan. Stream-0 only,
// allocation-free, graph-capturable.
// ---------------------------------------------------------------------------
extern "C" void kernel_launch(void* const* d_in, const int* in_sizes, int n_in,
                              void* d_out, int out_size) {
    const float* coeffs = (const float*)d_in[0];
    const float* times  = (const float*)d_in[1];
    const int*   mask   = (const int*)  d_in[2];
    const float* noise  = (const float*)d_in[3];
    const float* W_in   = (const float*)d_in[4];
    const float* b_in   = (const float*)d_in[5];
    const float* Wf1    = (const float*)d_in[6];
    const float* bf1    = (const float*)d_in[7];
    const float* Wf2    = (const float*)d_in[8];
    const float* bf2    = (const float*)d_in[9];
    const float* Wn     = (const float*)d_in[10];
    const float* bn     = (const float*)d_in[11];
    const float* Wg1    = (const float*)d_in[12];
    const float* bg1    = (const float*)d_in[13];
    const float* Wg2    = (const float*)d_in[14];
    const float* bg2    = (const float*)d_in[15];
    const float* W0     = (const float*)d_in[16];
    const float* b0     = (const float*)d_in[17];
    const float* Wd     = (const float*)d_in[18];
    const float* bd     = (const float*)d_in[19];
    const float* Wc     = (const float*)d_in[20];
    const float* bc     = (const float*)d_in[21];
    float* out = (float*)d_out;

    sde_prep_fuse<<<H_ + 2, 256>>>(W_in, b_in, Wf1, bf1, Wn, bn, Wg1, bg1);
    sde_prep_w2  <<<H_,     256>>>(Wf2, bf2, Wg2, bg2);
    sde_main     <<<G_, NTHR>>>(coeffs, times, mask, noise,
                                W0, b0, Wd, bd, Wc, bc, out);
}

// round 13
// speedup vs baseline: 1.2579x; 1.1608x over previous
#include <cuda_runtime.h>

#define B_   256
#define T_   1000
#define H_   256
#define DIN  64
#define DOUT 64
#define NC_  10
#define R_   4
#define NPAIR 64                /* row-groups (pairs) */
#define NCTA  (NPAIR * 2)       /* 128 CTAs, 1 per SM */
#define NTHR 512
#define STEPS (T_ - 1)
#define LOGITS_OFF ((size_t)B_ * (size_t)T_ * (size_t)DOUT)
#define KP   128                /* k-pairs total (256 k / 2) */
#define KQT  32                 /* k-pairs per thread-quarter (128/4) */
#define GRP  4                  /* k-pairs per prefetch group */
#define NGRP2 (KQT / GRP)       /* 8 groups */

// ---------------------------------------------------------------------------
// Device scratch (recomputed every call).
// g_WA[k2][j] = {Af[j][1+2k2], Ag[j][1+2k2], Af[j][2+2k2], Ag[j][2+2k2]}
// g_WB[k2][n] = {Wf2[n][2k2],  Wg2[n][2k2],  Wf2[n][2k2+1], Wg2[n][2k2+1]}
// ---------------------------------------------------------------------------
__device__ float4 g_WA[KP][H_];
__device__ float4 g_WB[KP][H_];
__device__ float2 g_a0 [H_];          // {Af[j][0], Ag[j][0]} (time row)
__device__ float2 g_cfg[H_];          // {Wf1@b_in+bf1, Wg1@bn+bg1}
__device__ float2 g_b2 [H_];          // {bf2, bg2}

// Exchange buffers + flags (zero-init; flags reset at kernel end each launch).
__device__ float2   g_xh [NPAIR][2][R_][128];   // h halves   {hf,hg}
__device__ float2   g_xy01[NPAIR][2][128];      // {y0,y1} halves
__device__ float2   g_xy23[NPAIR][2][128];      // {y2,y3} halves
__device__ float    g_xz [NPAIR][2][R_][128];   // z_final halves
__device__ unsigned g_fh [NPAIR][2];
__device__ unsigned g_fy [NPAIR][2];
__device__ unsigned g_fz [NPAIR][2];

// ---------------------------------------------------------------------------
// Packed fp32x2 + sync helpers.
// ---------------------------------------------------------------------------
typedef unsigned long long u64;
__device__ __forceinline__ void ffma2(u64& acc, u64 a, u64 b) {
    asm("fma.rn.f32x2 %0, %1, %2, %0;" : "+l"(acc) : "l"(a), "l"(b));
}
__device__ __forceinline__ u64 fadd2(u64 a, u64 b) {
    u64 r; asm("add.rn.f32x2 %0, %1, %2;" : "=l"(r) : "l"(a), "l"(b)); return r;
}
__device__ __forceinline__ u64 pack2(float lo, float hi) {
    u64 r;
    asm("mov.b64 %0, {%1, %2};" : "=l"(r)
        : "r"(__float_as_uint(lo)), "r"(__float_as_uint(hi)));
    return r;
}
__device__ __forceinline__ float lo2(u64 v) {
    return __uint_as_float((unsigned)(v & 0xffffffffull));
}
__device__ __forceinline__ float hi2(u64 v) {
    return __uint_as_float((unsigned)(v >> 32));
}
__device__ __forceinline__ u64 dup_lo(u64 v) { float f = lo2(v); return pack2(f, f); }
__device__ __forceinline__ u64 dup_hi(u64 v) { float f = hi2(v); return pack2(f, f); }
__device__ __forceinline__ float lipswish(float x) {
    return 0.909f * x / (1.0f + __expf(-x));
}
__device__ __forceinline__ unsigned ld_acq(const unsigned* p) {
    unsigned v;
    asm volatile("ld.acquire.gpu.global.u32 %0, [%1];" : "=r"(v) : "l"(p) : "memory");
    return v;
}
__device__ __forceinline__ void red_rel(unsigned* p) {
    asm volatile("red.release.gpu.global.add.u32 [%0], 1;" :: "l"(p) : "memory");
}
__device__ __forceinline__ float2 ld_f2_strong(const float2* p) {
    float2 v;
    asm volatile("ld.acquire.gpu.global.v2.f32 {%0,%1}, [%2];"
                 : "=f"(v.x), "=f"(v.y) : "l"(p) : "memory");
    return v;
}
__device__ __forceinline__ float ld_f_strong(const float* p) {
    float v;
    asm volatile("ld.acquire.gpu.global.f32 %0, [%1];" : "=f"(v) : "l"(p) : "memory");
    return v;
}
__device__ __forceinline__ void spin_ge(const unsigned* p, unsigned target) {
    while (ld_acq(p) < target) { }
}

// ---------------------------------------------------------------------------
// Prep 1: fuse the linear pairs; emit k-pair layout. (unchanged)
// ---------------------------------------------------------------------------
__global__ __launch_bounds__(256) void sde_prep_fuse(
    const float* __restrict__ W_in, const float* __restrict__ b_in,
    const float* __restrict__ Wf1,  const float* __restrict__ bf1,
    const float* __restrict__ Wn,   const float* __restrict__ bn,
    const float* __restrict__ Wg1,  const float* __restrict__ bg1)
{
    __shared__ float cin[H_], cn[H_];
    const int j = threadIdx.x;
    const int k = blockIdx.x;                 // 0..257
    if (k < H_ + 1) { cin[j] = W_in[j * (H_ + 1) + k]; cn[j] = Wn[j * (H_ + 1) + k]; }
    else            { cin[j] = b_in[j];                cn[j]  = bn[j]; }
    __syncthreads();
    const float* wf1r = Wf1 + (size_t)j * H_;
    const float* wg1r = Wg1 + (size_t)j * H_;
    float af = 0.f, ag = 0.f;
#pragma unroll 8
    for (int m = 0; m < H_; m++) {
        af = fmaf(wf1r[m], cin[m], af);
        ag = fmaf(wg1r[m], cn[m],  ag);
    }
    if (k == 0) {
        g_a0[j] = make_float2(af, ag);
    } else if (k <= H_) {
        const int k2 = (k - 1) >> 1, pos = (k - 1) & 1;
        float* p = reinterpret_cast<float*>(&g_WA[k2][j]);
        p[2 * pos] = af; p[2 * pos + 1] = ag;
    } else {
        g_cfg[j] = make_float2(af + bf1[j], ag + bg1[j]);
    }
}

// ---------------------------------------------------------------------------
// Prep 2: transpose second-layer weights into k-pair layout. (unchanged)
// ---------------------------------------------------------------------------
__global__ __launch_bounds__(256) void sde_prep_w2(
    const float* __restrict__ Wf2, const float* __restrict__ bf2,
    const float* __restrict__ Wg2, const float* __restrict__ bg2)
{
    const int n = threadIdx.x;
    const int k = blockIdx.x;                 // 0..255
    const int k2 = k >> 1, pos = k & 1;
    float* p = reinterpret_cast<float*>(&g_WB[k2][n]);
    p[2 * pos]     = Wf2[(size_t)n * H_ + k];
    p[2 * pos + 1] = Wg2[(size_t)n * H_ + k];
    if (k == 0) g_b2[n] = make_float2(bf2[n], bg2[n]);
}

// ---------------------------------------------------------------------------
// Main: 128 CTAs x 512 threads. Pair p = blockIdx>>1 owns rows 4p..4p+3;
// rank = blockIdx&1 owns output half j in [128*rank, 128*rank+128).
// Threads: j_local = tid&127, kq = tid>>7 (4-way k split, 32 k-pairs each).
// ---------------------------------------------------------------------------
__global__ __launch_bounds__(NTHR, 1) void sde_main(
    const float* __restrict__ coeffs, const float* __restrict__ times,
    const int*   __restrict__ mask,   const float* __restrict__ noise,
    const float* __restrict__ W0,     const float* __restrict__ b0,
    const float* __restrict__ Wd,     const float* __restrict__ bd,
    const float* __restrict__ Wc,     const float* __restrict__ bc,
    float* __restrict__ out)
{
    __shared__ float2 s_y01[H_];        // {y_row0, y_row1}[k]  (full 256 k)
    __shared__ float2 s_y23[H_];
    __shared__ float2 s_hfg[R_][H_];    // {hf_r, hg_r}[k]      (full 256 k)
    __shared__ u64    s_red[3][4][128]; // partials from kq 1..3
    __shared__ float2 s_part[8][DOUT];  // pred partials {rowA,rowB} per k-eighth
    __shared__ float  s_zf[R_][H_];
    __shared__ float  s_tm[T_];
    __shared__ float  s_x0[R_][DIN];
    __shared__ int    s_len[R_];

    const int tid   = threadIdx.x;
    const int pair  = blockIdx.x >> 1;
    const int rank  = blockIdx.x & 1;
    const int prank = rank ^ 1;
    const int row0  = pair * R_;
    const int jl    = tid & 127;
    const int j     = rank * 128 + jl;
    const int kq    = tid >> 7;             // 0..3
    const int kb2   = kq * KQT;             // first k-pair of this quarter

    // ---- init ----
    if (tid < R_) s_len[tid] = 0;
    for (int t = tid; t < T_; t += NTHR) s_tm[t] = times[t];
    if (tid < DIN) {
#pragma unroll
        for (int r = 0; r < R_; r++)
            s_x0[r][tid] = coeffs[(size_t)(row0 + r) * (size_t)(T_ - 1) * (4 * DIN) + tid];
    }
    __syncthreads();
    {
        int acc[R_] = {0, 0, 0, 0};
        for (int t = tid; t < T_; t += NTHR) {
#pragma unroll
            for (int r = 0; r < R_; r++) acc[r] += mask[(size_t)(row0 + r) * T_ + t];
        }
#pragma unroll
        for (int r = 0; r < R_; r++) atomicAdd(&s_len[r], acc[r]);
    }
    __syncthreads();
    int lastidx[R_];
#pragma unroll
    for (int r = 0; r < R_; r++) lastidx[r] = s_len[r] - 1;

    // ---- per-thread constants ----
    const float2 a0  = g_a0[j];
    const u64 p_af0 = pack2(a0.x, a0.x);
    const u64 p_ag0 = pack2(a0.y, a0.y);
    const float2 ccf = g_cfg[j];
    const float2 cb2 = g_b2[j];
    const int pm = tid & 63;
    const int pq = tid >> 6;                // 0..7 (pred k-eighth)

    // Wd slice in registers (32 consecutive k for output pm).
    float wdr[32];
    {
        const float* p = Wd + (size_t)pm * H_ + pq * 32;
#pragma unroll
        for (int kk = 0; kk < 32; kk++) wdr[kk] = p[kk];
    }

    // ---- y0 = x0 @ W0^T + b0 : threads 0..255 compute ALL j (both halves) ----
    if (tid < H_) {
        const int jj = tid;
        const float* w0r = W0 + (size_t)jj * DIN;
        const float  bb  = b0[jj];
        float a[R_];
#pragma unroll
        for (int r = 0; r < R_; r++) {
            float s = bb;
#pragma unroll 16
            for (int d = 0; d < DIN; d++) s = fmaf(s_x0[r][d], w0r[d], s);
            a[r] = s;
        }
        s_y01[jj] = make_float2(a[0], a[1]);
        s_y23[jj] = make_float2(a[2], a[3]);
    }
    __syncthreads();

    // kq0 threads own the y-state for their j (all 4 rows).
    float y[R_] = {0.f, 0.f, 0.f, 0.f};
    float zfin[R_] = {0.f, 0.f, 0.f, 0.f};
    if (kq == 0) {
        const float2 v01 = s_y01[j], v23 = s_y23[j];
        y[0] = v01.x; y[1] = v01.y; y[2] = v23.x; y[3] = v23.y;
#pragma unroll
        for (int r = 0; r < R_; r++) zfin[r] = y[r];    // covers lastidx == 0
    }
    float t_cur = s_tm[0];

    // ---- pred accumulate (all 512 threads; rank picks its 2 rows) ----
    auto pred_acc = [&]() {
        const float2* ya = rank ? s_y23 : s_y01;
        u64 acc = 0ull;
        const int kbase = pq * 32;
#pragma unroll
        for (int g = 0; g < 16; g++) {
            const ulonglong2 v = *reinterpret_cast<const ulonglong2*>(&ya[kbase + 2 * g]);
            ffma2(acc, v.x, pack2(wdr[2 * g],     wdr[2 * g]));
            ffma2(acc, v.y, pack2(wdr[2 * g + 1], wdr[2 * g + 1]));
        }
        s_part[pq][pm] = make_float2(lo2(acc), hi2(acc));
    };
    // ---- pred gather + store (kq==1 threads) ----
    auto pred_gather = [&](int idx) {
        const int t  = tid & 127;
        const int m  = t & 63;
        const int rr = t >> 6;
        const int row = 2 * rank + rr;
        float v = __ldg(&bd[m]);
#pragma unroll
        for (int qq = 0; qq < 8; qq++) {
            const float2 pp = s_part[qq][m];
            v += rr ? pp.y : pp.x;
        }
        out[(size_t)(row0 + row) * T_ * DOUT + (size_t)idx * DOUT + m] = v;
    };

    // ======================= main scan =======================
    for (int i = 0; ; i++) {
        // ---- top: ensure y(i) full in smem (peer half pulled from L2) ----
        if (i > 0 && kq == 3) {
            spin_ge(&g_fy[pair][prank], 128u * (unsigned)i);
            const int pj = prank * 128 + jl;
            s_y01[pj] = ld_f2_strong(&g_xy01[pair][prank][jl]);
            s_y23[pj] = ld_f2_strong(&g_xy23[pair][prank][jl]);
        }
        __syncthreads();                                  // B1

        pred_acc();                                       // partials for index i
        if (i == STEPS) break;

        // noise prefetch (kq0, own j)
        float eps[R_];
        if (kq == 0) {
            const float* np = noise + ((size_t)i * B_ + row0) * H_ + j;
#pragma unroll
            for (int r = 0; r < R_; r++) eps[r] = __ldg(np + (size_t)r * H_);
        }

        // ---------- phase A: pre-act = A @ [t; y] (own j, quarter k) ----------
        u64 af01, ag01, af23, ag23;
        if (kq == 0) {
            const u64 tt = pack2(t_cur, t_cur);
            af01 = 0ull; ffma2(af01, tt, p_af0);
            ag01 = 0ull; ffma2(ag01, tt, p_ag0);
            af23 = af01; ag23 = ag01;
        } else { af01 = ag01 = af23 = ag23 = 0ull; }
        {
            const ulonglong2* wa =
                reinterpret_cast<const ulonglong2*>(&g_WA[kb2][0]) + j;
            ulonglong2 wbuf[GRP];
#pragma unroll
            for (int p = 0; p < GRP; p++) wbuf[p] = wa[(size_t)p * H_];
#pragma unroll 1
            for (int blk = 0; blk < NGRP2; blk++) {
                ulonglong2 wn[GRP];
                if (blk < NGRP2 - 1) {
#pragma unroll
                    for (int p = 0; p < GRP; p++)
                        wn[p] = wa[(size_t)((blk + 1) * GRP + p) * H_];
                }
#pragma unroll
                for (int p = 0; p < GRP; p++) {
                    const int k2 = kb2 + blk * GRP + p;
                    const ulonglong2 v01 =
                        *reinterpret_cast<const ulonglong2*>(&s_y01[2 * k2]);
                    const ulonglong2 v23 =
                        *reinterpret_cast<const ulonglong2*>(&s_y23[2 * k2]);
                    const u64 df0 = dup_lo(wbuf[p].x), dg0 = dup_hi(wbuf[p].x);
                    const u64 df1 = dup_lo(wbuf[p].y), dg1 = dup_hi(wbuf[p].y);
                    ffma2(af01, v01.x, df0); ffma2(ag01, v01.x, dg0);
                    ffma2(af23, v23.x, df0); ffma2(ag23, v23.x, dg0);
                    ffma2(af01, v01.y, df1); ffma2(ag01, v01.y, dg1);
                    ffma2(af23, v23.y, df1); ffma2(ag23, v23.y, dg1);
                }
#pragma unroll
                for (int p = 0; p < GRP; p++) wbuf[p] = wn[p];
            }
        }
        if (kq > 0) {
            s_red[kq - 1][0][jl] = af01; s_red[kq - 1][1][jl] = ag01;
            s_red[kq - 1][2][jl] = af23; s_red[kq - 1][3][jl] = ag23;
        }
        __syncthreads();                                  // B3
        if (kq == 0) {
#pragma unroll
            for (int q = 0; q < 3; q++) {
                af01 = fadd2(af01, s_red[q][0][jl]); ag01 = fadd2(ag01, s_red[q][1][jl]);
                af23 = fadd2(af23, s_red[q][2][jl]); ag23 = fadd2(ag23, s_red[q][3][jl]);
            }
            const float2 h0 = make_float2(lipswish(lo2(af01) + ccf.x),
                                          lipswish(lo2(ag01) + ccf.y));
            const float2 h1 = make_float2(lipswish(hi2(af01) + ccf.x),
                                          lipswish(hi2(ag01) + ccf.y));
            const float2 h2 = make_float2(lipswish(lo2(af23) + ccf.x),
                                          lipswish(lo2(ag23) + ccf.y));
            const float2 h3 = make_float2(lipswish(hi2(af23) + ccf.x),
                                          lipswish(hi2(ag23) + ccf.y));
            s_hfg[0][j] = h0; s_hfg[1][j] = h1; s_hfg[2][j] = h2; s_hfg[3][j] = h3;
            g_xh[pair][rank][0][jl] = h0; g_xh[pair][rank][1][jl] = h1;
            g_xh[pair][rank][2][jl] = h2; g_xh[pair][rank][3][jl] = h3;
            red_rel(&g_fh[pair][rank]);
        } else if (kq == 1) {
            pred_gather(i);                               // hidden in reduce shadow
        } else if (kq == 2) {
            spin_ge(&g_fh[pair][prank], 128u * (unsigned)(i + 1));
            const int pj = prank * 128 + jl;
#pragma unroll
            for (int r = 0; r < R_; r++)
                s_hfg[r][pj] = ld_f2_strong(&g_xh[pair][prank][r][jl]);
        }
        __syncthreads();                                  // B5

        // ---------- phase B: {f,g} = h @ W2 (own n=j, quarter k) ----------
        u64 b0a = 0ull, b1a = 0ull, b2a = 0ull, b3a = 0ull;
        {
            const ulonglong2* wb =
                reinterpret_cast<const ulonglong2*>(&g_WB[kb2][0]) + j;
            ulonglong2 wbuf[GRP];
#pragma unroll
            for (int p = 0; p < GRP; p++) wbuf[p] = wb[(size_t)p * H_];
#pragma unroll 1
            for (int blk = 0; blk < NGRP2; blk++) {
                ulonglong2 wn[GRP];
                if (blk < NGRP2 - 1) {
#pragma unroll
                    for (int p = 0; p < GRP; p++)
                        wn[p] = wb[(size_t)((blk + 1) * GRP + p) * H_];
                }
#pragma unroll
                for (int p = 0; p < GRP; p++) {
                    const int k2 = kb2 + blk * GRP + p;
                    const ulonglong2 h0 =
                        *reinterpret_cast<const ulonglong2*>(&s_hfg[0][2 * k2]);
                    const ulonglong2 h1 =
                        *reinterpret_cast<const ulonglong2*>(&s_hfg[1][2 * k2]);
                    const ulonglong2 h2 =
                        *reinterpret_cast<const ulonglong2*>(&s_hfg[2][2 * k2]);
                    const ulonglong2 h3 =
                        *reinterpret_cast<const ulonglong2*>(&s_hfg[3][2 * k2]);
                    ffma2(b0a, h0.x, wbuf[p].x); ffma2(b0a, h0.y, wbuf[p].y);
                    ffma2(b1a, h1.x, wbuf[p].x); ffma2(b1a, h1.y, wbuf[p].y);
                    ffma2(b2a, h2.x, wbuf[p].x); ffma2(b2a, h2.y, wbuf[p].y);
                    ffma2(b3a, h3.x, wbuf[p].x); ffma2(b3a, h3.y, wbuf[p].y);
                }
#pragma unroll
                for (int p = 0; p < GRP; p++) wbuf[p] = wn[p];
            }
        }
        if (kq > 0) {
            s_red[kq - 1][0][jl] = b0a; s_red[kq - 1][1][jl] = b1a;
            s_red[kq - 1][2][jl] = b2a; s_red[kq - 1][3][jl] = b3a;
        }
        __syncthreads();                                  // B6
        if (kq == 0) {
#pragma unroll
            for (int q = 0; q < 3; q++) {
                b0a = fadd2(b0a, s_red[q][0][jl]); b1a = fadd2(b1a, s_red[q][1][jl]);
                b2a = fadd2(b2a, s_red[q][2][jl]); b3a = fadd2(b3a, s_red[q][3][jl]);
            }
            const float t_next = s_tm[i + 1];
            const float dt = t_next - t_cur;
            const float sd = sqrtf(dt);
            u64 fg[R_] = {b0a, b1a, b2a, b3a};
#pragma unroll
            for (int r = 0; r < R_; r++) {
                const float f = lo2(fg[r]) + cb2.x;
                const float g = hi2(fg[r]) + cb2.y;
                y[r] = fmaf(f, dt, fmaf(g, sd * eps[r], y[r]));
                if (i + 1 == lastidx[r]) zfin[r] = y[r];
            }
            const float2 v01 = make_float2(y[0], y[1]);
            const float2 v23 = make_float2(y[2], y[3]);
            s_y01[j] = v01; s_y23[j] = v23;               // own half (local)
            g_xy01[pair][rank][jl] = v01;                 // to peer (L2)
            g_xy23[pair][rank][jl] = v23;
            red_rel(&g_fy[pair][rank]);
        }
        t_cur = s_tm[i + 1];
        // no trailing barrier: B1 at next loop top publishes s_y01/s_y23
    }

    // ---- final pred gather (index = STEPS) + logits ----
    __syncthreads();
    if (kq == 1) pred_gather(STEPS);
    if (kq == 0) {
#pragma unroll
        for (int r = 0; r < R_; r++) {
            s_zf[r][j] = zfin[r];
            g_xz[pair][rank][r][jl] = zfin[r];
        }
        red_rel(&g_fz[pair][rank]);
    }
    if (kq == 2) {
        spin_ge(&g_fz[pair][prank], 128u);
        const int pj = prank * 128 + jl;
#pragma unroll
        for (int r = 0; r < R_; r++)
            s_zf[r][pj] = ld_f_strong(&g_xz[pair][prank][r][jl]);
    }
    __syncthreads();

    // logits for this rank's 2 rows
    if (tid < 2 * NC_) {
        const int rr = tid / NC_;
        const int c  = tid % NC_;
        const int row = 2 * rank + rr;
        const float* wcr = Wc + (size_t)c * H_;
        float a = bc[c];
#pragma unroll 8
        for (int k = 0; k < H_; k++) a = fmaf(s_zf[row][k], wcr[k], a);
        out[LOGITS_OFF + (size_t)(row0 + row) * NC_ + c] = a;
    }

    // ---- reset the flags this CTA consumed (peer-written) for next launch ----
    __syncthreads();
    if (tid == 0) {
        g_fh[pair][prank] = 0u;
        g_fy[pair][prank] = 0u;
        g_fz[pair][prank] = 0u;
    }
}

// ---------------------------------------------------------------------------
// Launch: prep kernels then the persistent paired scan. Stream-0 only,
// allocation-free, graph-capturable.
// ---------------------------------------------------------------------------
extern "C" void kernel_launch(void* const* d_in, const int* in_sizes, int n_in,
                              void* d_out, int out_size) {
    const float* coeffs = (const float*)d_in[0];
    const float* times  = (const float*)d_in[1];
    const int*   mask   = (const int*)  d_in[2];
    const float* noise  = (const float*)d_in[3];
    const float* W_in   = (const float*)d_in[4];
    const float* b_in   = (const float*)d_in[5];
    const float* Wf1    = (const float*)d_in[6];
    const float* bf1    = (const float*)d_in[7];
    const float* Wf2    = (const float*)d_in[8];
    const float* bf2    = (const float*)d_in[9];
    const float* Wn     = (const float*)d_in[10];
    const float* bn     = (const float*)d_in[11];
    const float* Wg1    = (const float*)d_in[12];
    const float* bg1    = (const float*)d_in[13];
    const float* Wg2    = (const float*)d_in[14];
    const float* bg2    = (const float*)d_in[15];
    const float* W0     = (const float*)d_in[16];
    const float* b0     = (const float*)d_in[17];
    const float* Wd     = (const float*)d_in[18];
    const float* bd     = (const float*)d_in[19];
    const float* Wc     = (const float*)d_in[20];
    const float* bc     = (const float*)d_in[21];
    float* out = (float*)d_out;

    sde_prep_fuse<<<H_ + 2, 256>>>(W_in, b_in, Wf1, bf1, Wn, bn, Wg1, bg1);
    sde_prep_w2  <<<H_,     256>>>(Wf2, bf2, Wg2, bg2);
    sde_main     <<<NCTA, NTHR>>>(coeffs, times, mask, noise,
                                  W0, b0, Wd, bd, Wc, bc, out);
}

// round 14
// speedup vs baseline: 1.3179x; 1.0477x over previous
#include <cuda_runtime.h>

#define B_   256
#define T_   1000
#define H_   256
#define DIN  64
#define DOUT 64
#define NC_  10
#define R_   4
#define NPAIR 64                /* row-groups (pairs) */
#define NCTA  (NPAIR * 2)       /* 128 CTAs, 1 per SM */
#define NTHR 512
#define STEPS (T_ - 1)
#define LOGITS_OFF ((size_t)B_ * (size_t)T_ * (size_t)DOUT)
#define KP   128                /* k-pairs total (256 k / 2) */
#define KQT  32                 /* k-pairs per thread-quarter (128/4) */
#define GRP  4                  /* k-pairs per prefetch group */
#define NGRP2 (KQT / GRP)       /* 8 groups */

#define CA   64                 /* cached WA k-pairs (quarters 0,1) */
#define CB   28                 /* cached WB k-pairs (quarter 0 partial) */
#define CACHE_BYTES ((CA + CB) * 128 * 16)   /* 184 KB dynamic smem */

// ---------------------------------------------------------------------------
// Device scratch (recomputed every call).
// g_WA[k2][j] = {Af[j][1+2k2], Ag[j][1+2k2], Af[j][2+2k2], Ag[j][2+2k2]}
// g_WB[k2][n] = {Wf2[n][2k2],  Wg2[n][2k2],  Wf2[n][2k2+1], Wg2[n][2k2+1]}
// ---------------------------------------------------------------------------
__device__ float4 g_WA[KP][H_];
__device__ float4 g_WB[KP][H_];
__device__ float2 g_a0 [H_];          // {Af[j][0], Ag[j][0]} (time row)
__device__ float2 g_cfg[H_];          // {Wf1@b_in+bf1, Wg1@bn+bg1}
__device__ float2 g_b2 [H_];          // {bf2, bg2}

// Exchange buffers + flags (zero-init; flags reset by their reader each launch).
__device__ float2   g_xh [NPAIR][2][R_][128];   // h halves   {hf,hg}
__device__ float2   g_xy01[NPAIR][2][128];      // {y0,y1} halves
__device__ float2   g_xy23[NPAIR][2][128];      // {y2,y3} halves
__device__ float    g_xz [NPAIR][2][R_][128];   // z_final halves
__device__ unsigned g_fh [NPAIR][2];
__device__ unsigned g_fy [NPAIR][2];
__device__ unsigned g_fz [NPAIR][2];

// ---------------------------------------------------------------------------
// Packed fp32x2 + sync helpers.
// ---------------------------------------------------------------------------
typedef unsigned long long u64;
__device__ __forceinline__ void ffma2(u64& acc, u64 a, u64 b) {
    asm("fma.rn.f32x2 %0, %1, %2, %0;" : "+l"(acc) : "l"(a), "l"(b));
}
__device__ __forceinline__ u64 fadd2(u64 a, u64 b) {
    u64 r; asm("add.rn.f32x2 %0, %1, %2;" : "=l"(r) : "l"(a), "l"(b)); return r;
}
__device__ __forceinline__ u64 pack2(float lo, float hi) {
    u64 r;
    asm("mov.b64 %0, {%1, %2};" : "=l"(r)
        : "r"(__float_as_uint(lo)), "r"(__float_as_uint(hi)));
    return r;
}
__device__ __forceinline__ float lo2(u64 v) {
    return __uint_as_float((unsigned)(v & 0xffffffffull));
}
__device__ __forceinline__ float hi2(u64 v) {
    return __uint_as_float((unsigned)(v >> 32));
}
__device__ __forceinline__ u64 dup_lo(u64 v) { float f = lo2(v); return pack2(f, f); }
__device__ __forceinline__ u64 dup_hi(u64 v) { float f = hi2(v); return pack2(f, f); }
__device__ __forceinline__ float lipswish(float x) {
    return 0.909f * x / (1.0f + __expf(-x));
}
__device__ __forceinline__ unsigned ld_acq(const unsigned* p) {
    unsigned v;
    asm volatile("ld.acquire.gpu.global.u32 %0, [%1];" : "=r"(v) : "l"(p) : "memory");
    return v;
}
__device__ __forceinline__ void red_rel(unsigned* p) {
    asm volatile("red.release.gpu.global.add.u32 [%0], 1;" :: "l"(p) : "memory");
}
__device__ __forceinline__ float2 ld_f2_strong(const float2* p) {
    float2 v;
    asm volatile("ld.acquire.gpu.global.v2.f32 {%0,%1}, [%2];"
                 : "=f"(v.x), "=f"(v.y) : "l"(p) : "memory");
    return v;
}
__device__ __forceinline__ float ld_f_strong(const float* p) {
    float v;
    asm volatile("ld.acquire.gpu.global.f32 %0, [%1];" : "=f"(v) : "l"(p) : "memory");
    return v;
}
__device__ __forceinline__ void spin_ge(const unsigned* p, unsigned target) {
    while (ld_acq(p) < target) { }
}

// ---------------------------------------------------------------------------
// Prep 1: fuse the linear pairs; emit k-pair layout.
// ---------------------------------------------------------------------------
__global__ __launch_bounds__(256) void sde_prep_fuse(
    const float* __restrict__ W_in, const float* __restrict__ b_in,
    const float* __restrict__ Wf1,  const float* __restrict__ bf1,
    const float* __restrict__ Wn,   const float* __restrict__ bn,
    const float* __restrict__ Wg1,  const float* __restrict__ bg1)
{
    __shared__ float cin[H_], cn[H_];
    const int j = threadIdx.x;
    const int k = blockIdx.x;                 // 0..257
    if (k < H_ + 1) { cin[j] = W_in[j * (H_ + 1) + k]; cn[j] = Wn[j * (H_ + 1) + k]; }
    else            { cin[j] = b_in[j];                cn[j]  = bn[j]; }
    __syncthreads();
    const float* wf1r = Wf1 + (size_t)j * H_;
    const float* wg1r = Wg1 + (size_t)j * H_;
    float af = 0.f, ag = 0.f;
#pragma unroll 8
    for (int m = 0; m < H_; m++) {
        af = fmaf(wf1r[m], cin[m], af);
        ag = fmaf(wg1r[m], cn[m],  ag);
    }
    if (k == 0) {
        g_a0[j] = make_float2(af, ag);
    } else if (k <= H_) {
        const int k2 = (k - 1) >> 1, pos = (k - 1) & 1;
        float* p = reinterpret_cast<float*>(&g_WA[k2][j]);
        p[2 * pos] = af; p[2 * pos + 1] = ag;
    } else {
        g_cfg[j] = make_float2(af + bf1[j], ag + bg1[j]);
    }
}

// ---------------------------------------------------------------------------
// Prep 2: transpose second-layer weights into k-pair layout.
// ---------------------------------------------------------------------------
__global__ __launch_bounds__(256) void sde_prep_w2(
    const float* __restrict__ Wf2, const float* __restrict__ bf2,
    const float* __restrict__ Wg2, const float* __restrict__ bg2)
{
    const int n = threadIdx.x;
    const int k = blockIdx.x;                 // 0..255
    const int k2 = k >> 1, pos = k & 1;
    float* p = reinterpret_cast<float*>(&g_WB[k2][n]);
    p[2 * pos]     = Wf2[(size_t)n * H_ + k];
    p[2 * pos + 1] = Wg2[(size_t)n * H_ + k];
    if (k == 0) g_b2[n] = make_float2(bf2[n], bg2[n]);
}

// ---------------------------------------------------------------------------
// Main: 128 CTAs x 512 threads. Pair p = blockIdx>>1 owns rows 4p..4p+3;
// rank = blockIdx&1 owns output half j in [128*rank, 128*rank+128).
// Threads: jl = tid&127, kq = tid>>7 (4-way k split, 32 k-pairs each).
// Dynamic smem pins WA k-pairs [0,CA) and WB k-pairs [0,CB) for own j-half.
// ---------------------------------------------------------------------------
__global__ __launch_bounds__(NTHR, 1) void sde_main(
    const float* __restrict__ coeffs, const float* __restrict__ times,
    const int*   __restrict__ mask,   const float* __restrict__ noise,
    const float* __restrict__ W0,     const float* __restrict__ b0,
    const float* __restrict__ Wd,     const float* __restrict__ bd,
    const float* __restrict__ Wc,     const float* __restrict__ bc,
    float* __restrict__ out)
{
    extern __shared__ float4 s_cache[];          // [CA+CB][128]
    float4* s_wa = s_cache;                      // [CA][128]
    float4* s_wb = s_cache + CA * 128;           // [CB][128]

    __shared__ float2 s_y01[H_];        // {y_row0, y_row1}[k]  (full 256 k)
    __shared__ float2 s_y23[H_];
    __shared__ float2 s_hfg[R_][H_];    // {hf_r, hg_r}[k]      (full 256 k)
    __shared__ u64    s_red[3][4][128]; // partials from kq 1..3
    __shared__ float2 s_part[8][DOUT];  // pred partials {rowA,rowB} per k-eighth
    __shared__ float  s_zf[R_][H_];
    __shared__ float  s_tm[T_];
    __shared__ float  s_x0[R_][DIN];
    __shared__ int    s_len[R_];

    const int tid   = threadIdx.x;
    const int pair  = blockIdx.x >> 1;
    const int rank  = blockIdx.x & 1;
    const int prank = rank ^ 1;
    const int row0  = pair * R_;
    const int jl    = tid & 127;
    const int j     = rank * 128 + jl;
    const int kq    = tid >> 7;             // 0..3
    const int kb2   = kq * KQT;             // first k-pair of this quarter

    // ---- init ----
    if (tid < R_) s_len[tid] = 0;
    for (int t = tid; t < T_; t += NTHR) s_tm[t] = times[t];
    if (tid < DIN) {
#pragma unroll
        for (int r = 0; r < R_; r++)
            s_x0[r][tid] = coeffs[(size_t)(row0 + r) * (size_t)(T_ - 1) * (4 * DIN) + tid];
    }
    // fill the weight cache (own j-half slices)
    for (int idx = tid; idx < CA * 128; idx += NTHR) {
        const int k2 = idx >> 7, jj = idx & 127;
        s_wa[(size_t)k2 * 128 + jj] = g_WA[k2][rank * 128 + jj];
    }
    for (int idx = tid; idx < CB * 128; idx += NTHR) {
        const int k2 = idx >> 7, jj = idx & 127;
        s_wb[(size_t)k2 * 128 + jj] = g_WB[k2][rank * 128 + jj];
    }
    __syncthreads();
    {
        int acc[R_] = {0, 0, 0, 0};
        for (int t = tid; t < T_; t += NTHR) {
#pragma unroll
            for (int r = 0; r < R_; r++) acc[r] += mask[(size_t)(row0 + r) * T_ + t];
        }
#pragma unroll
        for (int r = 0; r < R_; r++) atomicAdd(&s_len[r], acc[r]);
    }
    __syncthreads();
    int lastidx[R_];
#pragma unroll
    for (int r = 0; r < R_; r++) lastidx[r] = s_len[r] - 1;

    // ---- per-thread constants ----
    const float2 a0  = g_a0[j];
    const u64 p_af0 = pack2(a0.x, a0.x);
    const u64 p_ag0 = pack2(a0.y, a0.y);
    const float2 ccf = g_cfg[j];
    const float2 cb2 = g_b2[j];
    const int pm = tid & 63;
    const int pq = tid >> 6;                // 0..7 (pred k-eighth)

    // Wd slice in registers (32 consecutive k for output pm).
    float wdr[32];
    {
        const float* p = Wd + (size_t)pm * H_ + pq * 32;
#pragma unroll
        for (int kk = 0; kk < 32; kk++) wdr[kk] = p[kk];
    }

    // ---- y0 = x0 @ W0^T + b0 : threads 0..255 compute ALL j (both halves) ----
    if (tid < H_) {
        const int jj = tid;
        const float* w0r = W0 + (size_t)jj * DIN;
        const float  bb  = b0[jj];
        float a[R_];
#pragma unroll
        for (int r = 0; r < R_; r++) {
            float s = bb;
#pragma unroll 16
            for (int d = 0; d < DIN; d++) s = fmaf(s_x0[r][d], w0r[d], s);
            a[r] = s;
        }
        s_y01[jj] = make_float2(a[0], a[1]);
        s_y23[jj] = make_float2(a[2], a[3]);
    }
    __syncthreads();

    // kq0 threads own the y-state for their j (all 4 rows).
    float y[R_] = {0.f, 0.f, 0.f, 0.f};
    float zfin[R_] = {0.f, 0.f, 0.f, 0.f};
    if (kq == 0) {
        const float2 v01 = s_y01[j], v23 = s_y23[j];
        y[0] = v01.x; y[1] = v01.y; y[2] = v23.x; y[3] = v23.y;
#pragma unroll
        for (int r = 0; r < R_; r++) zfin[r] = y[r];    // covers lastidx == 0
    }
    float t_cur = s_tm[0];

    // ---- pred accumulate (all 512 threads; rank picks its 2 rows) ----
    auto pred_acc = [&]() {
        const float2* ya = rank ? s_y23 : s_y01;
        u64 acc = 0ull;
        const int kbase = pq * 32;
#pragma unroll
        for (int g = 0; g < 16; g++) {
            const ulonglong2 v = *reinterpret_cast<const ulonglong2*>(&ya[kbase + 2 * g]);
            ffma2(acc, v.x, pack2(wdr[2 * g],     wdr[2 * g]));
            ffma2(acc, v.y, pack2(wdr[2 * g + 1], wdr[2 * g + 1]));
        }
        s_part[pq][pm] = make_float2(lo2(acc), hi2(acc));
    };
    // ---- pred gather + store (kq==1 threads) ----
    auto pred_gather = [&](int idx) {
        const int t  = tid & 127;
        const int m  = t & 63;
        const int rr = t >> 6;
        const int row = 2 * rank + rr;
        float v = __ldg(&bd[m]);
#pragma unroll
        for (int qq = 0; qq < 8; qq++) {
            const float2 pp = s_part[qq][m];
            v += rr ? pp.y : pp.x;
        }
        out[(size_t)(row0 + row) * T_ * DOUT + (size_t)idx * DOUT + m] = v;
    };

    // ======================= main scan =======================
    for (int i = 0; ; i++) {
        // ---- top: ensure y(i) full in smem (peer half pulled from L2) ----
        if (i > 0 && kq == 3) {
            spin_ge(&g_fy[pair][prank], 128u * (unsigned)i);
            const int pj = prank * 128 + jl;
            s_y01[pj] = ld_f2_strong(&g_xy01[pair][prank][jl]);
            s_y23[pj] = ld_f2_strong(&g_xy23[pair][prank][jl]);
        }
        __syncthreads();                                  // B1

        pred_acc();                                       // partials for index i
        if (i == STEPS) break;

        // noise prefetch (kq0, own j)
        float eps[R_];
        if (kq == 0) {
            const float* np = noise + ((size_t)i * B_ + row0) * H_ + j;
#pragma unroll
            for (int r = 0; r < R_; r++) eps[r] = __ldg(np + (size_t)r * H_);
        }

        // ---------- phase A: pre-act = A @ [t; y] (own j, quarter k) ----------
        u64 af01, ag01, af23, ag23;
        if (kq == 0) {
            const u64 tt = pack2(t_cur, t_cur);
            af01 = 0ull; ffma2(af01, tt, p_af0);
            ag01 = 0ull; ffma2(ag01, tt, p_ag0);
            af23 = af01; ag23 = ag01;
        } else { af01 = ag01 = af23 = ag23 = 0ull; }
        if (kq < 2) {
            // fully cached quarters: pure smem
            const float4* ca = &s_wa[(size_t)kb2 * 128 + jl];
#pragma unroll 4
            for (int kk = 0; kk < KQT; kk++) {
                const int k2 = kb2 + kk;
                const ulonglong2 w = *reinterpret_cast<const ulonglong2*>(ca + (size_t)kk * 128);
                const ulonglong2 v01 =
                    *reinterpret_cast<const ulonglong2*>(&s_y01[2 * k2]);
                const ulonglong2 v23 =
                    *reinterpret_cast<const ulonglong2*>(&s_y23[2 * k2]);
                const u64 df0 = dup_lo(w.x), dg0 = dup_hi(w.x);
                const u64 df1 = dup_lo(w.y), dg1 = dup_hi(w.y);
                ffma2(af01, v01.x, df0); ffma2(ag01, v01.x, dg0);
                ffma2(af23, v23.x, df0); ffma2(ag23, v23.x, dg0);
                ffma2(af01, v01.y, df1); ffma2(ag01, v01.y, dg1);
                ffma2(af23, v23.y, df1); ffma2(ag23, v23.y, dg1);
            }
        } else {
            // streamed quarters
            const ulonglong2* wa =
                reinterpret_cast<const ulonglong2*>(&g_WA[kb2][0]) + j;
            ulonglong2 wbuf[GRP];
#pragma unroll
            for (int p = 0; p < GRP; p++) wbuf[p] = wa[(size_t)p * H_];
#pragma unroll 1
            for (int blk = 0; blk < NGRP2; blk++) {
                ulonglong2 wn[GRP];
                if (blk < NGRP2 - 1) {
#pragma unroll
                    for (int p = 0; p < GRP; p++)
                        wn[p] = wa[(size_t)((blk + 1) * GRP + p) * H_];
                }
#pragma unroll
                for (int p = 0; p < GRP; p++) {
                    const int k2 = kb2 + blk * GRP + p;
                    const ulonglong2 v01 =
                        *reinterpret_cast<const ulonglong2*>(&s_y01[2 * k2]);
                    const ulonglong2 v23 =
                        *reinterpret_cast<const ulonglong2*>(&s_y23[2 * k2]);
                    const u64 df0 = dup_lo(wbuf[p].x), dg0 = dup_hi(wbuf[p].x);
                    const u64 df1 = dup_lo(wbuf[p].y), dg1 = dup_hi(wbuf[p].y);
                    ffma2(af01, v01.x, df0); ffma2(ag01, v01.x, dg0);
                    ffma2(af23, v23.x, df0); ffma2(ag23, v23.x, dg0);
                    ffma2(af01, v01.y, df1); ffma2(ag01, v01.y, dg1);
                    ffma2(af23, v23.y, df1); ffma2(ag23, v23.y, dg1);
                }
#pragma unroll
                for (int p = 0; p < GRP; p++) wbuf[p] = wn[p];
            }
        }
        if (kq > 0) {
            s_red[kq - 1][0][jl] = af01; s_red[kq - 1][1][jl] = ag01;
            s_red[kq - 1][2][jl] = af23; s_red[kq - 1][3][jl] = ag23;
        }
        __syncthreads();                                  // B3
        if (kq == 0) {
#pragma unroll
            for (int q = 0; q < 3; q++) {
                af01 = fadd2(af01, s_red[q][0][jl]); ag01 = fadd2(ag01, s_red[q][1][jl]);
                af23 = fadd2(af23, s_red[q][2][jl]); ag23 = fadd2(ag23, s_red[q][3][jl]);
            }
            const float2 h0 = make_float2(lipswish(lo2(af01) + ccf.x),
                                          lipswish(lo2(ag01) + ccf.y));
            const float2 h1 = make_float2(lipswish(hi2(af01) + ccf.x),
                                          lipswish(hi2(ag01) + ccf.y));
            const float2 h2 = make_float2(lipswish(lo2(af23) + ccf.x),
                                          lipswish(lo2(ag23) + ccf.y));
            const float2 h3 = make_float2(lipswish(hi2(af23) + ccf.x),
                                          lipswish(hi2(ag23) + ccf.y));
            s_hfg[0][j] = h0; s_hfg[1][j] = h1; s_hfg[2][j] = h2; s_hfg[3][j] = h3;
            g_xh[pair][rank][0][jl] = h0; g_xh[pair][rank][1][jl] = h1;
            g_xh[pair][rank][2][jl] = h2; g_xh[pair][rank][3][jl] = h3;
            red_rel(&g_fh[pair][rank]);
        } else if (kq == 1) {
            pred_gather(i);                               // hidden in reduce shadow
        } else if (kq == 2) {
            spin_ge(&g_fh[pair][prank], 128u * (unsigned)(i + 1));
            const int pj = prank * 128 + jl;
#pragma unroll
            for (int r = 0; r < R_; r++)
                s_hfg[r][pj] = ld_f2_strong(&g_xh[pair][prank][r][jl]);
        }
        __syncthreads();                                  // B5

        // ---------- phase B: {f,g} = h @ W2 (own n=j, quarter k) ----------
        u64 b0a = 0ull, b1a = 0ull, b2a = 0ull, b3a = 0ull;
        if (kq == 0) {
            // cached part [0, CB)
            const float4* cbp = &s_wb[jl];
#pragma unroll 4
            for (int kk = 0; kk < CB; kk++) {
                const ulonglong2 w = *reinterpret_cast<const ulonglong2*>(cbp + (size_t)kk * 128);
                const ulonglong2 h0 =
                    *reinterpret_cast<const ulonglong2*>(&s_hfg[0][2 * kk]);
                const ulonglong2 h1 =
                    *reinterpret_cast<const ulonglong2*>(&s_hfg[1][2 * kk]);
                const ulonglong2 h2 =
                    *reinterpret_cast<const ulonglong2*>(&s_hfg[2][2 * kk]);
                const ulonglong2 h3 =
                    *reinterpret_cast<const ulonglong2*>(&s_hfg[3][2 * kk]);
                ffma2(b0a, h0.x, w.x); ffma2(b0a, h0.y, w.y);
                ffma2(b1a, h1.x, w.x); ffma2(b1a, h1.y, w.y);
                ffma2(b2a, h2.x, w.x); ffma2(b2a, h2.y, w.y);
                ffma2(b3a, h3.x, w.x); ffma2(b3a, h3.y, w.y);
            }
            // streamed tail [CB, KQT)
            const ulonglong2* wb =
                reinterpret_cast<const ulonglong2*>(&g_WB[CB][0]) + j;
            ulonglong2 wbuf[KQT - CB];
#pragma unroll
            for (int p = 0; p < KQT - CB; p++) wbuf[p] = wb[(size_t)p * H_];
#pragma unroll
            for (int p = 0; p < KQT - CB; p++) {
                const int k2 = CB + p;
                const ulonglong2 h0 =
                    *reinterpret_cast<const ulonglong2*>(&s_hfg[0][2 * k2]);
                const ulonglong2 h1 =
                    *reinterpret_cast<const ulonglong2*>(&s_hfg[1][2 * k2]);
                const ulonglong2 h2 =
                    *reinterpret_cast<const ulonglong2*>(&s_hfg[2][2 * k2]);
                const ulonglong2 h3 =
                    *reinterpret_cast<const ulonglong2*>(&s_hfg[3][2 * k2]);
                ffma2(b0a, h0.x, wbuf[p].x); ffma2(b0a, h0.y, wbuf[p].y);
                ffma2(b1a, h1.x, wbuf[p].x); ffma2(b1a, h1.y, wbuf[p].y);
                ffma2(b2a, h2.x, wbuf[p].x); ffma2(b2a, h2.y, wbuf[p].y);
                ffma2(b3a, h3.x, wbuf[p].x); ffma2(b3a, h3.y, wbuf[p].y);
            }
        } else {
            const ulonglong2* wb =
                reinterpret_cast<const ulonglong2*>(&g_WB[kb2][0]) + j;
            ulonglong2 wbuf[GRP];
#pragma unroll
            for (int p = 0; p < GRP; p++) wbuf[p] = wb[(size_t)p * H_];
#pragma unroll 1
            for (int blk = 0; blk < NGRP2; blk++) {
                ulonglong2 wn[GRP];
                if (blk < NGRP2 - 1) {
#pragma unroll
                    for (int p = 0; p < GRP; p++)
                        wn[p] = wb[(size_t)((blk + 1) * GRP + p) * H_];
                }
#pragma unroll
                for (int p = 0; p < GRP; p++) {
                    const int k2 = kb2 + blk * GRP + p;
                    const ulonglong2 h0 =
                        *reinterpret_cast<const ulonglong2*>(&s_hfg[0][2 * k2]);
                    const ulonglong2 h1 =
                        *reinterpret_cast<const ulonglong2*>(&s_hfg[1][2 * k2]);
                    const ulonglong2 h2 =
                        *reinterpret_cast<const ulonglong2*>(&s_hfg[2][2 * k2]);
                    const ulonglong2 h3 =
                        *reinterpret_cast<const ulonglong2*>(&s_hfg[3][2 * k2]);
                    ffma2(b0a, h0.x, wbuf[p].x); ffma2(b0a, h0.y, wbuf[p].y);
                    ffma2(b1a, h1.x, wbuf[p].x); ffma2(b1a, h1.y, wbuf[p].y);
                    ffma2(b2a, h2.x, wbuf[p].x); ffma2(b2a, h2.y, wbuf[p].y);
                    ffma2(b3a, h3.x, wbuf[p].x); ffma2(b3a, h3.y, wbuf[p].y);
                }
#pragma unroll
                for (int p = 0; p < GRP; p++) wbuf[p] = wn[p];
            }
        }
        if (kq > 0) {
            s_red[kq - 1][0][jl] = b0a; s_red[kq - 1][1][jl] = b1a;
            s_red[kq - 1][2][jl] = b2a; s_red[kq - 1][3][jl] = b3a;
        }
        __syncthreads();                                  // B6
        if (kq == 0) {
#pragma unroll
            for (int q = 0; q < 3; q++) {
                b0a = fadd2(b0a, s_red[q][0][jl]); b1a = fadd2(b1a, s_red[q][1][jl]);
                b2a = fadd2(b2a, s_red[q][2][jl]); b3a = fadd2(b3a, s_red[q][3][jl]);
            }
            const float t_next = s_tm[i + 1];
            const float dt = t_next - t_cur;
            const float sd = sqrtf(dt);
            u64 fg[R_] = {b0a, b1a, b2a, b3a};
#pragma unroll
            for (int r = 0; r < R_; r++) {
                const float f = lo2(fg[r]) + cb2.x;
                const float g = hi2(fg[r]) + cb2.y;
                y[r] = fmaf(f, dt, fmaf(g, sd * eps[r], y[r]));
                if (i + 1 == lastidx[r]) zfin[r] = y[r];
            }
            const float2 v01 = make_float2(y[0], y[1]);
            const float2 v23 = make_float2(y[2], y[3]);
            s_y01[j] = v01; s_y23[j] = v23;               // own half (local)
            g_xy01[pair][rank][jl] = v01;                 // to peer (L2)
            g_xy23[pair][rank][jl] = v23;
            red_rel(&g_fy[pair][rank]);
        }
        t_cur = s_tm[i + 1];
        // no trailing barrier: B1 at next loop top publishes s_y01/s_y23
    }

    // ---- final pred gather (index = STEPS) + logits ----
    __syncthreads();
    if (kq == 1) pred_gather(STEPS);
    if (kq == 0) {
#pragma unroll
        for (int r = 0; r < R_; r++) {
            s_zf[r][j] = zfin[r];
            g_xz[pair][rank][r][jl] = zfin[r];
        }
        red_rel(&g_fz[pair][rank]);
    }
    if (kq == 2) {
        spin_ge(&g_fz[pair][prank], 128u);
        const int pj = prank * 128 + jl;
#pragma unroll
        for (int r = 0; r < R_; r++)
            s_zf[r][pj] = ld_f_strong(&g_xz[pair][prank][r][jl]);
    }
    __syncthreads();

    // logits for this rank's 2 rows
    if (tid < 2 * NC_) {
        const int rr = tid / NC_;
        const int c  = tid % NC_;
        const int row = 2 * rank + rr;
        const float* wcr = Wc + (size_t)c * H_;
        float a = bc[c];
#pragma unroll 8
        for (int k = 0; k < H_; k++) a = fmaf(s_zf[row][k], wcr[k], a);
        out[LOGITS_OFF + (size_t)(row0 + row) * NC_ + c] = a;
    }

    // ---- reset the flags this CTA consumed (peer-written) for next launch ----
    __syncthreads();
    if (tid == 0) {
        g_fh[pair][prank] = 0u;
        g_fy[pair][prank] = 0u;
        g_fz[pair][prank] = 0u;
    }
}

// ---------------------------------------------------------------------------
// Launch: prep kernels then the persistent paired scan. Stream-0 only,
// allocation-free, graph-capturable.
// ---------------------------------------------------------------------------
extern "C" void kernel_launch(void* const* d_in, const int* in_sizes, int n_in,
                              void* d_out, int out_size) {
    const float* coeffs = (const float*)d_in[0];
    const float* times  = (const float*)d_in[1];
    const int*   mask   = (const int*)  d_in[2];
    const float* noise  = (const float*)d_in[3];
    const float* W_in   = (const float*)d_in[4];
    const float* b_in   = (const float*)d_in[5];
    const float* Wf1    = (const float*)d_in[6];
    const float* bf1    = (const float*)d_in[7];
    const float* Wf2    = (const float*)d_in[8];
    const float* bf2    = (const float*)d_in[9];
    const float* Wn     = (const float*)d_in[10];
    const float* bn     = (const float*)d_in[11];
    const float* Wg1    = (const float*)d_in[12];
    const float* bg1    = (const float*)d_in[13];
    const float* Wg2    = (const float*)d_in[14];
    const float* bg2    = (const float*)d_in[15];
    const float* W0     = (const float*)d_in[16];
    const float* b0     = (const float*)d_in[17];
    const float* Wd     = (const float*)d_in[18];
    const float* bd     = (const float*)d_in[19];
    const float* Wc     = (const float*)d_in[20];
    const float* bc     = (const float*)d_in[21];
    float* out = (float*)d_out;

    cudaFuncSetAttribute(sde_main, cudaFuncAttributeMaxDynamicSharedMemorySize,
                         CACHE_BYTES);

    sde_prep_fuse<<<H_ + 2, 256>>>(W_in, b_in, Wf1, bf1, Wn, bn, Wg1, bg1);
    sde_prep_w2  <<<H_,     256>>>(Wf2, bf2, Wg2, bg2);
    sde_main     <<<NCTA, NTHR, CACHE_BYTES>>>(coeffs, times, mask, noise,
                                               W0, b0, Wd, bd, Wc, bc, out);
}